// round 4
// baseline (speedup 1.0000x reference)
#include <cuda_runtime.h>

// EvolvingGNN: T=5, N=100000, E=1600000, D=H=64, FE=16.
//  (1) Only xs_out[-1] is consumed -> one GCN pass with the LSTM weight after 5 steps.
//  (2) Edge MLP factors: hid = relu(A[src] + B[dst] + ea@W1c + b1).
//  (3) LSTM: 5 steps inside one launch (block r owns W column r == h row r).
//  (4) Aggregation via CSR (histogram -> scan -> reorder -> warp-per-node gather),
//      NO feature atomics.
// edge_index arrives as int32 (JAX x64-disabled downgrades jnp.int64).

#define NMAX 100000
#define EMAX 1600000

__device__ float g_Wt[64 * 64];        // final evolved weight, [k][r]
__device__ int   g_cnt[NMAX];          // in-edge counts (excl self loop)
__device__ int   g_off[NMAX];          // CSR offsets (exclusive scan of cnt)
__device__ int   g_cur[NMAX];          // reorder cursors
__device__ int   g_bsum[256];          // block sums for scan
__device__ float g_dinv[NMAX];
__device__ int   g_csrc[EMAX];         // CSR source list
__device__ float g_xws[NMAX * 64];     // dinv[n] * (xs[4] @ W)[n]
__device__ float g_agg[NMAX * 64];     // relu(GCN aggregation)
__device__ float g_A[NMAX * 64];       // agg @ W1[0:64]
__device__ float g_B[NMAX * 64];       // agg @ W1[64:128]

__device__ __forceinline__ float sigmoidf(float x) { return 1.0f / (1.0f + expf(-x)); }

// ---------------- LSTM: all 5 steps in one launch ----------------
__global__ void lstm_all_kernel(const float* __restrict__ w0,
                                const float* __restrict__ w_ih,
                                const float* __restrict__ w_hh,
                                const float* __restrict__ b_ih,
                                const float* __restrict__ b_hh) {
    __shared__ float xb[64], cr[64], gate[256];
    int r = blockIdx.x;
    int tid = threadIdx.x;
    if (tid < 64) {
        xb[tid] = w0[tid * 64 + r];
        cr[tid] = 0.f;
    }
    float bsum = b_ih[tid] + b_hh[tid];
    const float4* wi = (const float4*)(w_ih + tid * 64);
    const float4* wh = (const float4*)(w_hh + tid * 64);
    for (int t = 0; t < 5; t++) {
        __syncthreads();
        float acc = bsum;
#pragma unroll
        for (int k4 = 0; k4 < 16; k4++) {
            float4 a = wi[k4];
            float4 b = wh[k4];
            float x0 = xb[4 * k4], x1 = xb[4 * k4 + 1], x2 = xb[4 * k4 + 2], x3 = xb[4 * k4 + 3];
            acc += a.x * x0 + a.y * x1 + a.z * x2 + a.w * x3;
            if (t > 0)   // hidden state == previous output column for t>=1; 0 at t==0
                acc += b.x * x0 + b.y * x1 + b.z * x2 + b.w * x3;
        }
        gate[tid] = acc;
        __syncthreads();
        if (tid < 64) {
            float gi = sigmoidf(gate[tid]);
            float gf = sigmoidf(gate[64 + tid]);
            float gg = tanhf(gate[128 + tid]);
            float go = sigmoidf(gate[192 + tid]);
            float cn = gf * cr[tid] + gi * gg;
            float hn = go * tanhf(cn);
            cr[tid] = cn;
            xb[tid] = hn;
        }
    }
    if (tid < 64) g_Wt[tid * 64 + r] = xb[tid];
}

// ---------------- CSR build ----------------
__global__ void zero_cnt_kernel(int n) {
    int i = blockIdx.x * blockDim.x + threadIdx.x;
    if (i < n) g_cnt[i] = 0;
}
__global__ void deg_count_kernel(const int* __restrict__ ei, int E) {
    int e = blockIdx.x * blockDim.x + threadIdx.x;
    if (e < E) atomicAdd(&g_cnt[ei[E + e]], 1);
}

// block-level exclusive scan (512 threads/block) -> partial offsets + block sums
__global__ void scan_block_kernel(int n) {
    __shared__ int wsum[16];
    int tid = threadIdx.x;
    int gid = blockIdx.x * 512 + tid;
    int lane = tid & 31, wid = tid >> 5;
    int v = (gid < n) ? g_cnt[gid] : 0;
    int inc = v;
#pragma unroll
    for (int o = 1; o < 32; o <<= 1) {
        int t = __shfl_up_sync(0xffffffffu, inc, o);
        if (lane >= o) inc += t;
    }
    if (lane == 31) wsum[wid] = inc;
    __syncthreads();
    if (wid == 0) {
        int ws = (lane < 16) ? wsum[lane] : 0;
#pragma unroll
        for (int o = 1; o < 16; o <<= 1) {
            int t = __shfl_up_sync(0xffffffffu, ws, o);
            if (lane >= o) ws += t;
        }
        if (lane < 16) wsum[lane] = ws;      // inclusive warp-sum scan
    }
    __syncthreads();
    int base = (wid > 0) ? wsum[wid - 1] : 0;
    if (gid < n) g_off[gid] = base + inc - v;
    if (tid == 0) g_bsum[blockIdx.x] = wsum[15];
}

// exclusive scan of block sums (single block, nb <= 256)
__global__ void scan_bsum_kernel(int nb) {
    __shared__ int wsum[8];
    int tid = threadIdx.x, lane = tid & 31, wid = tid >> 5;
    int v = (tid < nb) ? g_bsum[tid] : 0;
    int inc = v;
#pragma unroll
    for (int o = 1; o < 32; o <<= 1) {
        int t = __shfl_up_sync(0xffffffffu, inc, o);
        if (lane >= o) inc += t;
    }
    if (lane == 31) wsum[wid] = inc;
    __syncthreads();
    if (wid == 0) {
        int ws = (lane < 8) ? wsum[lane] : 0;
#pragma unroll
        for (int o = 1; o < 8; o <<= 1) {
            int t = __shfl_up_sync(0xffffffffu, ws, o);
            if (lane >= o) ws += t;
        }
        if (lane < 8) wsum[lane] = ws;
    }
    __syncthreads();
    int base = (wid > 0) ? wsum[wid - 1] : 0;
    if (tid < nb) g_bsum[tid] = base + inc - v;
}

// finalize offsets, cursors, dinv
__global__ void finalize_kernel(int n) {
    int i = blockIdx.x * blockDim.x + threadIdx.x;
    if (i < n) {
        int off = g_off[i] + g_bsum[i >> 9];
        g_off[i] = off;
        g_cur[i] = off;
        g_dinv[i] = rsqrtf((float)g_cnt[i] + 1.0f);
    }
}

__global__ void reorder_kernel(const int* __restrict__ ei, int E) {
    int e = blockIdx.x * blockDim.x + threadIdx.x;
    if (e < E) {
        int d = ei[E + e];
        int p = atomicAdd(&g_cur[d], 1);
        g_csrc[p] = ei[e];
    }
}

// ---------------- xws = dinv * (xs[last] @ W) ----------------
__global__ void xw_kernel(const float* __restrict__ x, int n) {
    __shared__ float Ws[64 * 64];
    __shared__ float Xs[16 * 64];
    int tid = threadIdx.x;
    for (int i = tid; i < 4096; i += 256) Ws[i] = g_Wt[i];
    int row0 = blockIdx.x * 16;
    for (int i = tid; i < 1024; i += 256) {
        int rr = i >> 6, cc = i & 63;
        int nn = row0 + rr;
        Xs[i] = (nn < n) ? x[(size_t)nn * 64 + cc] : 0.f;
    }
    __syncthreads();
    int jr = (tid & 15) * 4;
    int rr = tid >> 4;
    float a0 = 0, a1 = 0, a2 = 0, a3 = 0;
    const float* xr = Xs + rr * 64;
#pragma unroll 8
    for (int k = 0; k < 64; k++) {
        float xv = xr[k];
        const float* wk = Ws + k * 64 + jr;
        a0 += xv * wk[0]; a1 += xv * wk[1]; a2 += xv * wk[2]; a3 += xv * wk[3];
    }
    int nn = row0 + rr;
    if (nn < n) {
        float dv = g_dinv[nn];
        *(float4*)(g_xws + (size_t)nn * 64 + jr) =
            make_float4(dv * a0, dv * a1, dv * a2, dv * a3);
    }
}

// ---------------- warp-per-node gather aggregation (no atomics) ----------------
// agg[n] = relu( dinv[n] * ( xws[n] + sum_{e: col=n} xws[src_e] ) )
__global__ void aggregate_kernel(int n) {
    int w = (blockIdx.x * 256 + threadIdx.x) >> 5;
    int lane = threadIdx.x & 31;
    if (w >= n) return;
    const float2* x2 = (const float2*)g_xws;
    float2 acc = x2[(size_t)w * 32 + lane];          // self loop
    int off = g_off[w];
    int cnt = g_cnt[w];
    for (int base = 0; base < cnt; base += 32) {
        int m = cnt - base;
        if (m > 32) m = 32;
        int s = (lane < m) ? g_csrc[off + base + lane] : 0;
        for (int k = 0; k < m; k++) {
            int ss = __shfl_sync(0xffffffffu, s, k);
            float2 v = x2[(size_t)ss * 32 + lane];
            acc.x += v.x;
            acc.y += v.y;
        }
    }
    float dv = g_dinv[w];
    ((float2*)g_agg)[(size_t)w * 32 + lane] =
        make_float2(fmaxf(dv * acc.x, 0.f), fmaxf(dv * acc.y, 0.f));
}

// ---------------- A,B = agg @ W1[0:64], @ W1[64:128]  (agg already relu'd) ----------------
__global__ void ab_kernel(const float* __restrict__ w1, int n) {
    __shared__ float Wa[64 * 64];
    __shared__ float Wb[64 * 64];
    __shared__ float Xs[16 * 64];
    int tid = threadIdx.x;
    for (int i = tid; i < 4096; i += 256) { Wa[i] = w1[i]; Wb[i] = w1[4096 + i]; }
    int row0 = blockIdx.x * 16;
    for (int i = tid; i < 1024; i += 256) {
        int rr = i >> 6, cc = i & 63;
        int nn = row0 + rr;
        Xs[i] = (nn < n) ? g_agg[(size_t)nn * 64 + cc] : 0.f;
    }
    __syncthreads();
    int jr = (tid & 15) * 4;
    int rr = tid >> 4;
    float a0 = 0, a1 = 0, a2 = 0, a3 = 0;
    float b0 = 0, b1v = 0, b2v = 0, b3 = 0;
    const float* xr = Xs + rr * 64;
#pragma unroll 4
    for (int k = 0; k < 64; k++) {
        float xv = xr[k];
        const float* wa = Wa + k * 64 + jr;
        const float* wb = Wb + k * 64 + jr;
        a0 += xv * wa[0]; a1 += xv * wa[1]; a2 += xv * wa[2]; a3 += xv * wa[3];
        b0 += xv * wb[0]; b1v += xv * wb[1]; b2v += xv * wb[2]; b3 += xv * wb[3];
    }
    int nn = row0 + rr;
    if (nn < n) {
        *(float4*)(g_A + (size_t)nn * 64 + jr) = make_float4(a0, a1, a2, a3);
        *(float4*)(g_B + (size_t)nn * 64 + jr) = make_float4(b0, b1v, b2v, b3);
    }
}

// ---------------- Edge MLP: logit = relu(A[src]+B[dst]+ea@W1c+b1) . w2 + b2 ----------------
// Warp per edge. Lanes 0-15 load A chunk (float4), lanes 16-31 load B chunk;
// shfl_xor(16) exchange. Each lane evaluates 2 hidden dims with Wc/b1/w2 in registers.
__global__ void edge_mlp_kernel(const int* __restrict__ ei,
                                const float* __restrict__ ea,
                                const float* __restrict__ w1,
                                const float* __restrict__ b1,
                                const float* __restrict__ w2,
                                const float* __restrict__ b2,
                                float* __restrict__ out, int E) {
    int tid = threadIdx.x;
    int lane = tid & 31;
    int half = lane & 15;
    bool hiB = lane >= 16;
    int j0 = half * 4 + (hiB ? 2 : 0);          // this lane's two hidden dims: j0, j0+1
    float wc0[16], wc1[16];
#pragma unroll
    for (int k = 0; k < 16; k++) {
        wc0[k] = w1[8192 + k * 64 + j0];
        wc1[k] = w1[8192 + k * 64 + j0 + 1];
    }
    float bb0 = b1[j0], bb1 = b1[j0 + 1];
    float ww0 = w2[j0], ww1 = w2[j0 + 1];
    float b2v = b2[0];

    int e = (blockIdx.x * 256 + tid) >> 5;
    if (e >= E) return;
    int src = ei[e];
    int dst = ei[E + e];
    float4 mine = hiB ? ((const float4*)g_B)[(size_t)dst * 16 + half]
                      : ((const float4*)g_A)[(size_t)src * 16 + half];
    float4 other;
    other.x = __shfl_xor_sync(0xffffffffu, mine.x, 16);
    other.y = __shfl_xor_sync(0xffffffffu, mine.y, 16);
    other.z = __shfl_xor_sync(0xffffffffu, mine.z, 16);
    other.w = __shfl_xor_sync(0xffffffffu, mine.w, 16);
    // lane's hidden pre-activations for dims j0, j0+1
    float h0, h1;
    if (hiB) {
        h0 = mine.z + other.z + bb0;
        h1 = mine.w + other.w + bb1;
    } else {
        h0 = mine.x + other.x + bb0;
        h1 = mine.y + other.y + bb1;
    }
    float eav = (lane < 16) ? ea[(size_t)e * 16 + lane] : 0.f;
#pragma unroll
    for (int k = 0; k < 16; k++) {
        float ek = __shfl_sync(0xffffffffu, eav, k);
        h0 += ek * wc0[k];
        h1 += ek * wc1[k];
    }
    h0 = fmaxf(h0, 0.f);
    h1 = fmaxf(h1, 0.f);
    float p = h0 * ww0 + h1 * ww1;
#pragma unroll
    for (int off = 16; off; off >>= 1) p += __shfl_xor_sync(0xffffffffu, p, off);
    if (lane == 0) out[e] = p + b2v;
}

extern "C" void kernel_launch(void* const* d_in, const int* in_sizes, int n_in,
                              void* d_out, int out_size) {
    const float* xs = (const float*)d_in[0];
    const int* ei = (const int*)d_in[1];            // int32 (JAX x64 disabled)
    const float* ea = (const float*)d_in[2];
    const float* init_w = (const float*)d_in[3];
    const float* w_ih = (const float*)d_in[4];
    const float* w_hh = (const float*)d_in[5];
    const float* b_ih = (const float*)d_in[6];
    const float* b_hh = (const float*)d_in[7];
    const float* w1 = (const float*)d_in[8];
    const float* b1 = (const float*)d_in[9];
    const float* w2 = (const float*)d_in[10];
    const float* b2 = (const float*)d_in[11];
    float* out = (float*)d_out;

    int N = in_sizes[0] / (5 * 64);
    int E = in_sizes[1] / 2;
    int nScanBlocks = (N + 511) / 512;

    // 1) LSTM weight evolution (single launch)
    lstm_all_kernel<<<64, 256>>>(init_w, w_ih, w_hh, b_ih, b_hh);

    // 2) CSR build: histogram -> scan -> finalize -> reorder
    zero_cnt_kernel<<<(N + 255) / 256, 256>>>(N);
    deg_count_kernel<<<(E + 255) / 256, 256>>>(ei, E);
    scan_block_kernel<<<nScanBlocks, 512>>>(N);
    scan_bsum_kernel<<<1, 256>>>(nScanBlocks);
    finalize_kernel<<<(N + 255) / 256, 256>>>(N);
    reorder_kernel<<<(E + 255) / 256, 256>>>(ei, E);

    // 3) xws = dinv * (xs[4] @ W)
    xw_kernel<<<(N + 15) / 16, 256>>>(xs + (size_t)4 * N * 64, N);

    // 4) warp-per-node gather aggregation (no atomics), relu fused
    aggregate_kernel<<<(N * 32 + 255) / 256, 256>>>(N);

    // 5) per-node MLP halves
    ab_kernel<<<(N + 15) / 16, 256>>>(w1, N);

    // 6) per-edge MLP + logit
    edge_mlp_kernel<<<(E + 7) / 8, 256>>>(ei, ea, w1, b1, w2, b2, out, E);
}